// round 3
// baseline (speedup 1.0000x reference)
#include <cuda_runtime.h>
#include <cuda_bf16.h>
#include <cstdint>

#define BATCH 128
#define SEQ   2048
#define INF   128
#define HID   256
#define OUTF  128
#define CHUNKS 24          // K = 384 = 24 * 16
#define RS    400          // B-buffer row stride in halves
#define NROW  8            // MMA N dim (only col 0 real)
#define BUFH  (NROW * RS)  // halves per buffer

// fragment-permutation: position of k%16 inside a 16-half chunk so that
// lane q (=lane%4) reads its 4 B-fragment halves {2q,2q+1,2q+8,2q+9} with one LDS.64
__device__ __forceinline__ int posmap(int i) {
    return (i & 1) + ((i >> 1) & 3) * 4 + ((i >> 3) & 1) * 2;
}

__device__ __forceinline__ uint32_t packbf(float lo, float hi) {
    __nv_bfloat162 v = __floats2bfloat162_rn(lo, hi);
    return *reinterpret_cast<uint32_t*>(&v);
}

__device__ __forceinline__ void mma16816(float* c,
                                         const uint32_t* a,
                                         uint32_t b0, uint32_t b1) {
    asm volatile(
        "mma.sync.aligned.m16n8k16.row.col.f32.bf16.bf16.f32 "
        "{%0,%1,%2,%3}, {%4,%5,%6,%7}, {%8,%9}, {%0,%1,%2,%3};\n"
        : "+f"(c[0]), "+f"(c[1]), "+f"(c[2]), "+f"(c[3])
        : "r"(a[0]), "r"(a[1]), "r"(a[2]), "r"(a[3]), "r"(b0), "r"(b1));
}

__global__ void __launch_bounds__(256, 1)
elman_kernel(const float* __restrict__ x,
             const float* __restrict__ Win,
             const float* __restrict__ bin,
             const float* __restrict__ Wrec,
             const float* __restrict__ Wout,
             const float* __restrict__ bout,
             float* __restrict__ out)
{
    __shared__ __align__(16) __nv_bfloat16 sB[2][BUFH]; // ping-pong B operand
    __shared__ float h32_s[HID];
    __shared__ float red[HID];

    const int tid  = threadIdx.x;
    const int b    = blockIdx.x;
    const int warp = tid >> 5;
    const int lane = tid & 31;
    const int qr   = lane >> 2;        // 0..7  (B n-index)
    const int qc   = (lane & 3) * 2;   // 0,2,4,6 (k base within chunk)

    // zero both B buffers (rows 1..7 of B stay zero forever)
    for (int i = tid; i < 2 * BUFH; i += 256)
        ((__nv_bfloat16*)sB)[i] = __float2bfloat16(0.f);

    const float binr = bin[tid];

    // ---- persistent A fragments: A_cat = [W_in | W_rec] ----
    uint32_t Af[CHUNKS][2][4];
#pragma unroll
    for (int kc = 0; kc < CHUNKS; kc++) {
#pragma unroll
        for (int m = 0; m < 2; m++) {
            const int r = warp * 32 + m * 16 + qr;
            const int c = kc * 16 + qc;
            const float* rowA  = (c < INF) ? (Win + (size_t)r * INF + c)
                                           : (Wrec + (size_t)r * HID + (c - INF));
            const float* rowA8 = (c < INF) ? (Win + (size_t)(r + 8) * INF + c)
                                           : (Wrec + (size_t)(r + 8) * HID + (c - INF));
            Af[kc][m][0] = packbf(rowA[0],  rowA[1]);
            Af[kc][m][1] = packbf(rowA8[0], rowA8[1]);
            Af[kc][m][2] = packbf(rowA[8],  rowA[9]);
            Af[kc][m][3] = packbf(rowA8[8], rowA8[9]);
        }
    }

    // ---- x_0 into buffer 0 (h region zero = h_init) ----
    const float* xb = x + (size_t)b * SEQ * INF;
    if (tid < INF)
        sB[0][(tid >> 4) * 16 + posmap(tid & 15)] = __float2bfloat16(xb[tid]);

    // accumulators: even-chunk and odd-chunk chains (4 chains/warp)
    float ce[2][4], co[2][4];
#pragma unroll
    for (int m = 0; m < 2; m++)
#pragma unroll
        for (int i = 0; i < 4; i++) { ce[m][i] = 0.f; co[m][i] = 0.f; }

    // per-lane B-fragment base pointers (one LDS.64 per chunk)
    const uint2* bp0 = reinterpret_cast<const uint2*>(&sB[0][qr * RS + (lane & 3) * 4]);
    const uint2* bp1 = reinterpret_cast<const uint2*>(&sB[1][qr * RS + (lane & 3) * 4]);

    // h / x destination pointers (row 0 of B: x at chunks 0-7, h at chunks 8-23)
    __nv_bfloat16* hd0 = &sB[0][(8 + (tid >> 4)) * 16 + posmap(tid & 15)];
    __nv_bfloat16* xd0 = &sB[0][(tid >> 4) * 16 + posmap(tid & 15)];

    __syncthreads();

    float hlast = 0.f;

    for (int t = 0; t < SEQ; t++) {
        const int cur = t & 1;
        const uint2* bp = cur ? bp1 : bp0;

        // prefetch next timestep's x (hidden under mma phase)
        float xv = 0.f;
        if (tid < INF && t + 1 < SEQ) xv = xb[(size_t)(t + 1) * INF + tid];

        // ---- mma phase: z = A_cat @ [x_t ; h], 24 k16-chunks, 4 chains ----
#pragma unroll
        for (int kc = 0; kc < CHUNKS; kc += 2) {
            const uint2 bb0 = bp[kc * 4];
            const uint2 bb1 = bp[(kc + 1) * 4];
            mma16816(ce[0], Af[kc][0],     bb0.x, bb0.y);
            mma16816(ce[1], Af[kc][1],     bb0.x, bb0.y);
            mma16816(co[0], Af[kc + 1][0], bb1.x, bb1.y);
            mma16816(co[1], Af[kc + 1][1], bb1.x, bb1.y);
        }

        // ---- merge parity chains (col-0 values live in lanes l&3==0) ----
        const float z0 = ce[0][0] + co[0][0];   // m0 rows 0-7
        const float z1 = ce[0][2] + co[0][2];   // m0 rows 8-15
        const float z2 = ce[1][0] + co[1][0];   // m1 rows 16-23
        const float z3 = ce[1][2] + co[1][2];   // m1 rows 24-31
#pragma unroll
        for (int m = 0; m < 2; m++)
#pragma unroll
            for (int i = 0; i < 4; i++) { ce[m][i] = 0.f; co[m][i] = 0.f; }

        // ---- shuffle z so lane L holds row warp*32+L (no smem, no extra bar) ----
        const int src = (lane & 7) * 4;
        const float v0 = __shfl_sync(0xffffffffu, z0, src);
        const float v1 = __shfl_sync(0xffffffffu, z1, src);
        const float v2 = __shfl_sync(0xffffffffu, z2, src);
        const float v3 = __shfl_sync(0xffffffffu, z3, src);
        float zz = (lane < 16) ? ((lane < 8) ? v0 : v1)
                               : ((lane < 24) ? v2 : v3);
        zz += binr;
        const float h = __fdividef(1.f, 1.f + __expf(-zz));
        hlast = h;

        // ---- write h (and prefetched x) into the NEXT buffer ----
        const __nv_bfloat16 hb = __float2bfloat16(h);
        if (cur) {           // next buffer is 0
            hd0[0] = hb;
            if (tid < INF) xd0[0] = __float2bfloat16(xv);
        } else {             // next buffer is 1
            hd0[BUFH] = hb;
            if (tid < INF) xd0[BUFH] = __float2bfloat16(xv);
        }
        __syncthreads();     // single barrier per step
    }

    h32_s[tid] = hlast;
    __syncthreads();

    // ---- final projection: y[b] = h @ Wout^T + bout (fp32) ----
    {
        const int o    = tid & (OUTF - 1);
        const int half = tid >> 7;
        const float* wrow = Wout + (size_t)o * HID + half * 128;
        const float* hh   = h32_s + half * 128;
        float acc = 0.f;
#pragma unroll 8
        for (int k = 0; k < 128; k++) acc += hh[k] * __ldg(&wrow[k]);
        red[tid] = acc;
    }
    __syncthreads();
    if (tid < OUTF)
        out[(size_t)b * OUTF + tid] = red[tid] + red[tid + 128] + bout[tid];
}

extern "C" void kernel_launch(void* const* d_in, const int* in_sizes, int n_in,
                              void* d_out, int out_size)
{
    const float* x    = (const float*)d_in[0];
    const float* Win  = (const float*)d_in[1];
    const float* bin  = (const float*)d_in[2];
    const float* Wrec = (const float*)d_in[3];
    const float* Wout = (const float*)d_in[4];
    const float* bout = (const float*)d_in[5];
    float* out = (float*)d_out;

    elman_kernel<<<BATCH, 256>>>(x, Win, bin, Wrec, Wout, bout, out);
}